// round 8
// baseline (speedup 1.0000x reference)
#include <cuda_runtime.h>
#include <cuda_fp16.h>

#define NN 50000
#define EE 500000
#define FF 64
#define HH 4

// ---------------- scratch (device globals; no allocation allowed) ----------------
__device__ __align__(16) __half2 g_projh[(size_t)NN * 128]; // [n][h][f] fp16, 25.6 MB
__device__ __align__(16) float2  g_psum2[(size_t)NN * 32];  // [n][f] fp32 sum over heads, 12.8 MB
__device__ __align__(16) float g_sc[NN * 8];                // node scores [rad h0..3, tan h0..3]
__device__ __align__(16) float g_exs[(size_t)EE * 8];       // exp(logit), receiver-sorted, 16 MB
__device__ __align__(16) float g_acc[NN * FF];              // per-node message (head-mean folded)
__device__ int g_sedge[EE];                                 // sender id, receiver-sorted
__device__ int g_deg[NN];
__device__ int g_off[NN + 1];
__device__ int g_cur[NN];

// packed fp32 FMA: d = a*b + c  (2 lanes per instruction, FFMA2)
__device__ __forceinline__ float2 fma2(float2 a, float2 b, float2 c) {
    float2 d;
    asm("fma.rn.f32x2 %0, %1, %2, %3;"
        : "=l"(reinterpret_cast<unsigned long long&>(d))
        : "l"(reinterpret_cast<unsigned long long&>(a)),
          "l"(reinterpret_cast<unsigned long long&>(b)),
          "l"(reinterpret_cast<unsigned long long&>(c)));
    return d;
}

// ---------------- init: zero degree histogram ----------------
__global__ void init_kernel() {
    int i = blockIdx.x * blockDim.x + threadIdx.x;
    if (i < NN) g_deg[i] = 0;
}

// ---------------- histogram of receivers ----------------
__global__ void hist_kernel(const int* __restrict__ ei) {
    int i = blockIdx.x * blockDim.x + threadIdx.x;
    if (i < EE) atomicAdd(&g_deg[ei[EE + i]], 1);
}

// ---------------- single-block exclusive scan over degrees ----------------
__global__ void scan_kernel() {
    __shared__ int sm[1024];
    int tid = threadIdx.x;
    const int C = (NN + 1023) / 1024;           // 49
    int base = tid * C;
    int hi = min(base + C, NN);
    int s = 0;
    for (int i = base; i < hi; i++) s += g_deg[i];
    sm[tid] = s;
    __syncthreads();
    // Hillis-Steele inclusive scan
    for (int off = 1; off < 1024; off <<= 1) {
        int v = (tid >= off) ? sm[tid - off] : 0;
        __syncthreads();
        sm[tid] += v;
        __syncthreads();
    }
    int run = (tid == 0) ? 0 : sm[tid - 1];
    for (int i = base; i < hi; i++) {
        g_off[i] = run;
        g_cur[i] = run;
        run += g_deg[i];
    }
    if (tid == 1023) g_off[NN] = sm[1023];
}

// ---------------- per-node projection (fp16 out + fp32 head-sum) + node scores ----------
// proj[n,h,g] = sum_f x[n,f] * w_proj[h,f,g]     -> g_projh (fp16), g_psum2 (fp32 sum_h)
// sc[n,i]     = sum_f x[n,f] * wrt[i,f],  wrt[i,f] = sum_g w_proj[h,f,g]*score[h,g]
#define PT 32  // nodes per tile (PT=64 measured WORSE in R6 — register pressure)
__global__ void proj_kernel(const float* __restrict__ x,
                            const float* __restrict__ w_proj,
                            const float* __restrict__ rs,
                            const float* __restrict__ ts) {
    extern __shared__ float sh[];
    float2* wsh2 = (float2*)sh;          // [64][128] pairs: wsh2[f*128 + h*32 + gp] = w[h,f,2gp..2gp+1]
    float*  xs   = sh + 64 * 256;        // [PT][65] padded
    float*  wrt  = xs + PT * 65;         // [8][65]  padded

    int tid = threadIdx.x;

    // load weights as float2 pairs, transposed to [f][h*32+gp]
    for (int idx = tid; idx < 64 * 128; idx += 256) {
        int f = idx >> 7, p = idx & 127;
        int h = p >> 5, gp = p & 31;
        wsh2[idx] = ((const float2*)w_proj)[h * 2048 + f * 32 + gp];
    }
    __syncthreads();

    // wrt[i][f]
    for (int e = tid; e < 8 * 64; e += 256) {
        int i = e >> 6, f = e & 63;
        int h = i & 3;
        const float* sc = (i < 4) ? rs : ts;
        float s = 0.f;
        #pragma unroll 8
        for (int gp = 0; gp < 32; gp++) {
            float2 w = wsh2[f * 128 + h * 32 + gp];
            s += w.x * sc[h * 64 + 2 * gp] + w.y * sc[h * 64 + 2 * gp + 1];
        }
        wrt[i * 65 + f] = s;
    }

    int pg = tid & 31;       // g-pair column (covers g = 2pg, 2pg+1 of every head)
    int ng = tid >> 5;       // node group (4 nodes each)
    int ntiles = (NN + PT - 1) / PT;

    for (int tile = blockIdx.x; tile < ntiles; tile += gridDim.x) {
        int n0 = tile * PT;
        __syncthreads();  // orders wrt/xs across tiles
        for (int idx = tid; idx < PT * 64; idx += 256) {
            int nd = idx >> 6, f = idx & 63;
            int n = n0 + nd;
            xs[nd * 65 + f] = (n < NN) ? x[n * 64 + f] : 0.f;
        }
        __syncthreads();

        float2 acc[4][4];  // [node j][head h] — pair (2pg,2pg+1)
        #pragma unroll
        for (int j = 0; j < 4; j++)
            #pragma unroll
            for (int h = 0; h < 4; h++) acc[j][h] = make_float2(0.f, 0.f);

        #pragma unroll 4
        for (int f = 0; f < 64; f++) {
            float2 w0 = wsh2[f * 128 + pg];
            float2 w1 = wsh2[f * 128 + 32 + pg];
            float2 w2 = wsh2[f * 128 + 64 + pg];
            float2 w3 = wsh2[f * 128 + 96 + pg];
            #pragma unroll
            for (int j = 0; j < 4; j++) {
                float xv = xs[(ng * 4 + j) * 65 + f];
                float2 xx = make_float2(xv, xv);
                acc[j][0] = fma2(w0, xx, acc[j][0]);
                acc[j][1] = fma2(w1, xx, acc[j][1]);
                acc[j][2] = fma2(w2, xx, acc[j][2]);
                acc[j][3] = fma2(w3, xx, acc[j][3]);
            }
        }

        #pragma unroll
        for (int j = 0; j < 4; j++) {
            int n = n0 + ng * 4 + j;
            if (n < NN) {
                __half2* op = g_projh + (size_t)n * 128;   // [h*32 + pg]
                op[pg]      = __float22half2_rn(acc[j][0]);
                op[32 + pg] = __float22half2_rn(acc[j][1]);
                op[64 + pg] = __float22half2_rn(acc[j][2]);
                op[96 + pg] = __float22half2_rn(acc[j][3]);
                float2 ps;
                ps.x = acc[j][0].x + acc[j][1].x + acc[j][2].x + acc[j][3].x;
                ps.y = acc[j][0].y + acc[j][1].y + acc[j][2].y + acc[j][3].y;
                g_psum2[(size_t)n * 32 + pg] = ps;
            }
        }

        // node scores: thread -> (node tid/8, score-index tid%8)
        int nd2 = tid >> 3, i2 = tid & 7;
        int n2 = n0 + nd2;
        if (n2 < NN) {
            float s = 0.f;
            #pragma unroll 8
            for (int f = 0; f < 64; f++) s += xs[nd2 * 65 + f] * wrt[i2 * 65 + f];
            g_sc[n2 * 8 + i2] = s;
        }
    }
}

// ---------------- edge pass 1: exp(logits), scatter into receiver-sorted slots -------
__global__ void edge_pass1(const int* __restrict__ ei,
                           const float* __restrict__ elen,
                           const float* __restrict__ rds) {
    int i = blockIdx.x * blockDim.x + threadIdx.x;
    if (i >= EE) return;
    float scale = rds[0];
    int s = ei[i], r = ei[EE + i];
    const float4* scp = (const float4*)g_sc;
    float4 a0 = scp[s * 2], a1 = scp[s * 2 + 1];
    float4 b0 = scp[r * 2], b1 = scp[r * 2 + 1];
    float d = scale * elen[i];
    float4 er, et;
    er.x = __expf(a0.x - b0.x - d); er.y = __expf(a0.y - b0.y - d);
    er.z = __expf(a0.z - b0.z - d); er.w = __expf(a0.w - b0.w - d);
    et.x = __expf(a1.x - b1.x);     et.y = __expf(a1.y - b1.y);
    et.z = __expf(a1.z - b1.z);     et.w = __expf(a1.w - b1.w);
    int pos = atomicAdd(&g_cur[r], 1);
    g_sedge[pos] = s;
    float4* exp_ptr = (float4*)(g_exs + (size_t)pos * 8);
    exp_ptr[0] = er;
    exp_ptr[1] = et;
}

// ---------------- edge pass 2: per-receiver segmented softmax + gather-accumulate ----
// 8 lanes per receiver node; lane sub owns softmax index sub and f-chunk [8sub,8sub+7]
__global__ void edge_pass2(int dummy) {
    int t = blockIdx.x * blockDim.x + threadIdx.x;
    int n = t >> 3, sub = t & 7;
    if (n >= NN) return;
    int lane = threadIdx.x & 31;
    unsigned gm = 0xFFu << (lane & 24);   // mask of this 8-lane group

    int beg = g_off[n], end = g_off[n + 1];

    // denominators: lane sub sums its own softmax channel over the segment
    float denom = 0.f;
    for (int p = beg; p < end; p++) denom += g_exs[(size_t)p * 8 + sub];
    float inv = (end > beg) ? __fdividef(1.f, denom) : 0.f;

    float v[8];
    #pragma unroll
    for (int k = 0; k < 8; k++) v[k] = 0.f;

    for (int p = beg; p < end; p++) {
        float al = g_exs[(size_t)p * 8 + sub] * inv;
        int s = g_sedge[p];
        const uint4* ph = (const uint4*)g_projh + (size_t)s * 32;
        uint4 q0 = ph[sub], q1 = ph[8 + sub], q2 = ph[16 + sub], q3 = ph[24 + sub];

        // combine rad/tan: lanes h and h+4 hold the pair
        float al2 = al + __shfl_xor_sync(gm, al, 4, 8);
        float w0 = 0.25f * __shfl_sync(gm, al2, 0, 8);
        float w1 = 0.25f * __shfl_sync(gm, al2, 1, 8);
        float w2 = 0.25f * __shfl_sync(gm, al2, 2, 8);
        float w3 = 0.25f * __shfl_sync(gm, al2, 3, 8);

        #pragma unroll
        for (int h = 0; h < 4; h++) {
            uint4 q = (h == 0) ? q0 : (h == 1) ? q1 : (h == 2) ? q2 : q3;
            float w = (h == 0) ? w0 : (h == 1) ? w1 : (h == 2) ? w2 : w3;
            float2 c0 = __half22float2(*(const __half2*)&q.x);
            float2 c1 = __half22float2(*(const __half2*)&q.y);
            float2 c2 = __half22float2(*(const __half2*)&q.z);
            float2 c3 = __half22float2(*(const __half2*)&q.w);
            v[0] += w * c0.x; v[1] += w * c0.y;
            v[2] += w * c1.x; v[3] += w * c1.y;
            v[4] += w * c2.x; v[5] += w * c2.y;
            v[6] += w * c3.x; v[7] += w * c3.y;
        }
    }
    float4* dst = (float4*)(g_acc + (size_t)n * 64 + sub * 8);
    dst[0] = make_float4(v[0], v[1], v[2], v[3]);
    dst[1] = make_float4(v[4], v[5], v[6], v[7]);
}

// ---------------- epilogue: msg, residual + out-GEMM (packed f32x2) ----------------
// warp handles 4 nodes; lane handles output-column pair (2lane, 2lane+1)
// msg[n,f] = g_acc[n,f] - 0.5*flag*psum[n,f]
__global__ void epilogue_kernel(const float* __restrict__ x,
                                const float* __restrict__ w_out,
                                float* __restrict__ out) {
    __shared__ float2 wsh2[64 * 32];     // [f][gp]
    __shared__ float msh[8][4][64];
    int tid = threadIdx.x, lane = tid & 31, wid = tid >> 5;
    for (int idx = tid; idx < 2048; idx += 256) wsh2[idx] = ((const float2*)w_out)[idx];
    __syncthreads();

    int base = (blockIdx.x * 8 + wid) * 4;
    if (base >= NN) return;

    const float* psum = (const float*)g_psum2;
    #pragma unroll
    for (int j = 0; j < 4; j++) {
        int n = base + j;
        if (n >= NN) { msh[wid][j][lane] = 0.f; msh[wid][j][lane + 32] = 0.f; continue; }
        float ne = (g_deg[n] > 0) ? 0.5f : 0.f;
        #pragma unroll
        for (int k = 0; k < 2; k++) {
            int f = lane + k * 32;
            msh[wid][j][f] = g_acc[n * 64 + f] - ne * psum[(size_t)n * 64 + f];
        }
    }
    __syncwarp();

    float2 a2[4];
    #pragma unroll
    for (int j = 0; j < 4; j++) {
        int n = base + j;
        a2[j] = (n < NN) ? ((const float2*)x)[n * 32 + lane] : make_float2(0.f, 0.f);
    }
    #pragma unroll 4
    for (int f = 0; f < 64; f++) {
        float2 w = wsh2[f * 32 + lane];
        #pragma unroll
        for (int j = 0; j < 4; j++) {
            float m = msh[wid][j][f];
            a2[j] = fma2(w, make_float2(m, m), a2[j]);
        }
    }
    #pragma unroll
    for (int j = 0; j < 4; j++) {
        int n = base + j;
        if (n < NN) ((float2*)out)[n * 32 + lane] = a2[j];
    }
}

// ---------------- launch ----------------
extern "C" void kernel_launch(void* const* d_in, const int* in_sizes, int n_in,
                              void* d_out, int out_size) {
    const float* x      = (const float*)d_in[0];
    const int*   ei     = (const int*)d_in[1];
    // d_in[2] = edge_vec (unused by reference)
    const float* elen   = (const float*)d_in[3];
    const float* w_proj = (const float*)d_in[4];
    const float* rs     = (const float*)d_in[5];
    const float* ts     = (const float*)d_in[6];
    const float* rds    = (const float*)d_in[7];
    const float* w_out  = (const float*)d_in[8];
    float* out = (float*)d_out;

    const int shmem = (64 * 256 + PT * 65 + 8 * 65) * (int)sizeof(float);  // 75,936 B
    cudaFuncSetAttribute(proj_kernel, cudaFuncAttributeMaxDynamicSharedMemorySize, shmem);

    init_kernel<<<(NN + 255) / 256, 256>>>();
    hist_kernel<<<(EE + 255) / 256, 256>>>(ei);
    scan_kernel<<<1, 1024>>>();
    proj_kernel<<<296, 256, shmem>>>(x, w_proj, rs, ts);
    edge_pass1<<<(EE + 255) / 256, 256>>>(ei, elen, rds);
    edge_pass2<<<(NN * 8 + 255) / 256, 256>>>(0);
    epilogue_kernel<<<(NN + 31) / 32, 256>>>(x, w_out, out);
}

// round 10
// speedup vs baseline: 1.1212x; 1.1212x over previous
#include <cuda_runtime.h>
#include <cuda_fp16.h>

#define NN 50000
#define EE 500000
#define FF 64
#define HH 4

// ---------------- scratch (device globals; no allocation allowed) ----------------
__device__ __align__(16) __half2 g_projh[(size_t)NN * 128]; // [n][h][f] fp16, 25.6 MB
__device__ __align__(16) float2  g_psum2[(size_t)NN * 32];  // [n][f] fp32 sum over heads, 12.8 MB
__device__ __align__(16) float g_sc[NN * 8];                // node scores [rad h0..3, tan h0..3]
__device__ __align__(16) float g_ssum[NN * 8];              // softmax denominators
__device__ __align__(16) float g_ex[(size_t)EE * 8];        // per-edge exp(logit)
__device__ __align__(16) float g_acc[NN * FF];              // scattered messages (head-mean folded)

__device__ __forceinline__ void red_add_v4(float* p, float4 v) {
    asm volatile("red.global.add.v4.f32 [%0], {%1,%2,%3,%4};"
                 :: "l"(p), "f"(v.x), "f"(v.y), "f"(v.z), "f"(v.w) : "memory");
}

// packed fp32 FMA: d = a*b + c  (2 lanes per instruction, FFMA2)
__device__ __forceinline__ float2 fma2(float2 a, float2 b, float2 c) {
    float2 d;
    asm("fma.rn.f32x2 %0, %1, %2, %3;"
        : "=l"(reinterpret_cast<unsigned long long&>(d))
        : "l"(reinterpret_cast<unsigned long long&>(a)),
          "l"(reinterpret_cast<unsigned long long&>(b)),
          "l"(reinterpret_cast<unsigned long long&>(c)));
    return d;
}

// ---------------- init: zero accumulators ----------------
__global__ void init_kernel() {
    int i = blockIdx.x * blockDim.x + threadIdx.x;
    int stride = gridDim.x * blockDim.x;
    for (int j = i; j < NN * FF; j += stride) g_acc[j] = 0.f;
    for (int j = i; j < NN * 8; j += stride) g_ssum[j] = 0.f;
}

// ---------------- per-node projection (fp16 weights in smem for occupancy) ----------
// proj[n,h,g] = sum_f x[n,f] * w_proj[h,f,g]  -> g_projh (fp16), g_psum2 (fp32 sum_h)
// sc[n,i]     = sum_f x[n,f] * wrt[i,f]; wrt computed from FP32 global weights
// (softmax-logit path must stay fp32-accurate; only the GEMM uses fp16 weights).
// SMEM layout (floats): [0,8192) wh2 (64*128 half2 = 32KB), [8192,+PT*65) xs, then wrt.
#define PT 32  // nodes per tile
#define WH_FLOATS (64 * 128 * 2 / 2)   // 64*128 half2 = 32768 B = 8192 floats
__global__ void __launch_bounds__(256, 4)
proj_kernel(const float* __restrict__ x,
            const float* __restrict__ w_proj,
            const float* __restrict__ rs,
            const float* __restrict__ ts) {
    extern __shared__ float sh[];
    __half2* wh2 = (__half2*)sh;                  // [64][128]: wh2[f*128 + h*32 + gp] = w[h,f,2gp..2gp+1]
    float*   xs  = sh + WH_FLOATS;                // [PT][65] padded
    float*   wrt = xs + PT * 65;                  // [8][65] padded

    int tid = threadIdx.x;

    // load weights (fp32 global -> fp16 shared), transposed to [f][h*32+gp]
    for (int idx = tid; idx < 64 * 128; idx += 256) {
        int f = idx >> 7, p = idx & 127;
        int h = p >> 5, gp = p & 31;
        float2 w = ((const float2*)w_proj)[h * 2048 + f * 32 + gp];
        wh2[idx] = __float22half2_rn(w);
    }

    // wrt[i][f] from FP32 global weights (accuracy-critical)
    for (int e = tid; e < 8 * 64; e += 256) {
        int i = e >> 6, f = e & 63;
        int h = i & 3;
        const float* sc = (i < 4) ? rs : ts;
        const float* wrow = w_proj + h * 4096 + f * 64;
        float s = 0.f;
        #pragma unroll 8
        for (int g = 0; g < 64; g++) s += wrow[g] * sc[h * 64 + g];
        wrt[i * 65 + f] = s;
    }

    int pg = tid & 31;       // g-pair column (covers g = 2pg, 2pg+1 of every head)
    int ng = tid >> 5;       // node group (4 nodes each)
    int ntiles = (NN + PT - 1) / PT;

    for (int tile = blockIdx.x; tile < ntiles; tile += gridDim.x) {
        int n0 = tile * PT;
        __syncthreads();  // orders wrt/xs across tiles (and weight load on first)
        for (int idx = tid; idx < PT * 64; idx += 256) {
            int nd = idx >> 6, f = idx & 63;
            int n = n0 + nd;
            xs[nd * 65 + f] = (n < NN) ? x[n * 64 + f] : 0.f;
        }
        __syncthreads();

        float2 acc[4][4];  // [node j][head h] — pair (2pg,2pg+1)
        #pragma unroll
        for (int j = 0; j < 4; j++)
            #pragma unroll
            for (int h = 0; h < 4; h++) acc[j][h] = make_float2(0.f, 0.f);

        #pragma unroll 4
        for (int f = 0; f < 64; f++) {
            float2 w0 = __half22float2(wh2[f * 128 + pg]);
            float2 w1 = __half22float2(wh2[f * 128 + 32 + pg]);
            float2 w2 = __half22float2(wh2[f * 128 + 64 + pg]);
            float2 w3 = __half22float2(wh2[f * 128 + 96 + pg]);
            #pragma unroll
            for (int j = 0; j < 4; j++) {
                float xv = xs[(ng * 4 + j) * 65 + f];
                float2 xx = make_float2(xv, xv);
                acc[j][0] = fma2(w0, xx, acc[j][0]);
                acc[j][1] = fma2(w1, xx, acc[j][1]);
                acc[j][2] = fma2(w2, xx, acc[j][2]);
                acc[j][3] = fma2(w3, xx, acc[j][3]);
            }
        }

        #pragma unroll
        for (int j = 0; j < 4; j++) {
            int n = n0 + ng * 4 + j;
            if (n < NN) {
                __half2* op = g_projh + (size_t)n * 128;   // [h*32 + pg]
                op[pg]      = __float22half2_rn(acc[j][0]);
                op[32 + pg] = __float22half2_rn(acc[j][1]);
                op[64 + pg] = __float22half2_rn(acc[j][2]);
                op[96 + pg] = __float22half2_rn(acc[j][3]);
                float2 ps;
                ps.x = acc[j][0].x + acc[j][1].x + acc[j][2].x + acc[j][3].x;
                ps.y = acc[j][0].y + acc[j][1].y + acc[j][2].y + acc[j][3].y;
                g_psum2[(size_t)n * 32 + pg] = ps;
            }
        }

        // node scores: thread -> (node tid/8, score-index tid%8); fp32 path
        int nd2 = tid >> 3, i2 = tid & 7;
        int n2 = n0 + nd2;
        if (n2 < NN) {
            float s = 0.f;
            #pragma unroll 8
            for (int f = 0; f < 64; f++) s += xs[nd2 * 65 + f] * wrt[i2 * 65 + f];
            g_sc[n2 * 8 + i2] = s;
        }
    }
}

// ---------------- edge pass 1: exp(logits), accumulate softmax sums ----------------
__global__ void edge_pass1(const int* __restrict__ ei,
                           const float* __restrict__ elen,
                           const float* __restrict__ rds) {
    int i = blockIdx.x * blockDim.x + threadIdx.x;
    if (i >= EE) return;
    float scale = rds[0];
    int s = ei[i], r = ei[EE + i];
    const float4* scp = (const float4*)g_sc;
    float4 a0 = scp[s * 2], a1 = scp[s * 2 + 1];
    float4 b0 = scp[r * 2], b1 = scp[r * 2 + 1];
    float d = scale * elen[i];
    float4 er, et;
    er.x = __expf(a0.x - b0.x - d); er.y = __expf(a0.y - b0.y - d);
    er.z = __expf(a0.z - b0.z - d); er.w = __expf(a0.w - b0.w - d);
    et.x = __expf(a1.x - b1.x);     et.y = __expf(a1.y - b1.y);
    et.z = __expf(a1.z - b1.z);     et.w = __expf(a1.w - b1.w);
    float4* exp_ptr = (float4*)(g_ex + (size_t)i * 8);
    exp_ptr[0] = er;
    exp_ptr[1] = et;
    red_add_v4(g_ssum + r * 8, er);
    red_add_v4(g_ssum + r * 8 + 4, et);
}

// ---------------- edge pass 2: alpha-weighted scatter of fp16 sender proj ------------
// 8 lanes per edge (4 edges per warp); lane sub handles f-chunk [8sub, 8sub+7] of
// every head via one LDG.128 per head (R6 version — measured best at 43.8us)
__global__ void edge_pass2(const int* __restrict__ ei) {
    int lane = threadIdx.x & 31;
    int warp = (blockIdx.x * blockDim.x + threadIdx.x) >> 5;
    int grp = lane >> 3, sub = lane & 7;
    int e = warp * 4 + grp;
    if (e >= EE) return;
    int s = ei[e], r = ei[EE + e];

    // every lane computes one of the 8 alphas
    float a = __fdividef(g_ex[(size_t)e * 8 + sub], g_ssum[r * 8 + sub]);
    // combined per-head weight = alpha_rad[h] + alpha_tan[h]  (shuffle within 8-lane group)
    const unsigned m = 0xffffffffu;
    float w0 = __shfl_sync(m, a, 0, 8) + __shfl_sync(m, a, 4, 8);
    float w1 = __shfl_sync(m, a, 1, 8) + __shfl_sync(m, a, 5, 8);
    float w2 = __shfl_sync(m, a, 2, 8) + __shfl_sync(m, a, 6, 8);
    float w3 = __shfl_sync(m, a, 3, 8) + __shfl_sync(m, a, 7, 8);

    // fp16 row: 256 halves = 32 uint4; head h occupies uint4 [h*8, h*8+7]
    const uint4* ph = (const uint4*)g_projh + (size_t)s * 32;
    uint4 q0 = ph[sub], q1 = ph[8 + sub], q2 = ph[16 + sub], q3 = ph[24 + sub];

    float v[8];
    #pragma unroll
    for (int k = 0; k < 8; k++) v[k] = 0.f;

    #pragma unroll
    for (int h = 0; h < 4; h++) {
        uint4 q = (h == 0) ? q0 : (h == 1) ? q1 : (h == 2) ? q2 : q3;
        float w = (h == 0) ? w0 : (h == 1) ? w1 : (h == 2) ? w2 : w3;
        float2 c0 = __half22float2(*(const __half2*)&q.x);
        float2 c1 = __half22float2(*(const __half2*)&q.y);
        float2 c2 = __half22float2(*(const __half2*)&q.z);
        float2 c3 = __half22float2(*(const __half2*)&q.w);
        v[0] += w * c0.x; v[1] += w * c0.y;
        v[2] += w * c1.x; v[3] += w * c1.y;
        v[4] += w * c2.x; v[5] += w * c2.y;
        v[6] += w * c3.x; v[7] += w * c3.y;
    }
    // 0.25 = head mean, applied once here
    float4 vA = make_float4(0.25f * v[0], 0.25f * v[1], 0.25f * v[2], 0.25f * v[3]);
    float4 vB = make_float4(0.25f * v[4], 0.25f * v[5], 0.25f * v[6], 0.25f * v[7]);
    float* dst = g_acc + r * 64 + sub * 8;
    red_add_v4(dst, vA);
    red_add_v4(dst + 4, vB);
}

// ---------------- epilogue: msg, residual + out-GEMM (packed f32x2) ----------------
// warp handles 4 nodes; lane handles output-column pair (2lane, 2lane+1)
// msg[n,f] = g_acc[n,f] - 0.5*flag*psum[n,f]
__global__ void epilogue_kernel(const float* __restrict__ x,
                                const float* __restrict__ w_out,
                                float* __restrict__ out) {
    __shared__ float2 wsh2[64 * 32];     // [f][gp]
    __shared__ float msh[8][4][64];
    int tid = threadIdx.x, lane = tid & 31, wid = tid >> 5;
    for (int idx = tid; idx < 2048; idx += 256) wsh2[idx] = ((const float2*)w_out)[idx];
    __syncthreads();

    int base = (blockIdx.x * 8 + wid) * 4;
    if (base >= NN) return;

    const float* psum = (const float*)g_psum2;
    #pragma unroll
    for (int j = 0; j < 4; j++) {
        int n = base + j;
        if (n >= NN) { msh[wid][j][lane] = 0.f; msh[wid][j][lane + 32] = 0.f; continue; }
        float ne = (g_ssum[n * 8] > 0.f) ? 0.5f : 0.f;
        #pragma unroll
        for (int k = 0; k < 2; k++) {
            int f = lane + k * 32;
            msh[wid][j][f] = g_acc[n * 64 + f] - ne * psum[(size_t)n * 64 + f];
        }
    }
    __syncwarp();

    float2 a2[4];
    #pragma unroll
    for (int j = 0; j < 4; j++) {
        int n = base + j;
        a2[j] = (n < NN) ? ((const float2*)x)[n * 32 + lane] : make_float2(0.f, 0.f);
    }
    #pragma unroll 4
    for (int f = 0; f < 64; f++) {
        float2 w = wsh2[f * 32 + lane];
        #pragma unroll
        for (int j = 0; j < 4; j++) {
            float m = msh[wid][j][f];
            a2[j] = fma2(w, make_float2(m, m), a2[j]);
        }
    }
    #pragma unroll
    for (int j = 0; j < 4; j++) {
        int n = base + j;
        if (n < NN) ((float2*)out)[n * 32 + lane] = a2[j];
    }
}

// ---------------- launch ----------------
extern "C" void kernel_launch(void* const* d_in, const int* in_sizes, int n_in,
                              void* d_out, int out_size) {
    const float* x      = (const float*)d_in[0];
    const int*   ei     = (const int*)d_in[1];
    // d_in[2] = edge_vec (unused by reference)
    const float* elen   = (const float*)d_in[3];
    const float* w_proj = (const float*)d_in[4];
    const float* rs     = (const float*)d_in[5];
    const float* ts     = (const float*)d_in[6];
    const float* rds    = (const float*)d_in[7];
    const float* w_out  = (const float*)d_in[8];
    float* out = (float*)d_out;

    // smem (floats): 8192 (fp16 weights, 32KB) + PT*65 (xs) + 8*65 (wrt) = 43,168 B
    const int shmem = (WH_FLOATS + PT * 65 + 8 * 65) * (int)sizeof(float);
    cudaFuncSetAttribute(proj_kernel, cudaFuncAttributeMaxDynamicSharedMemorySize, shmem);

    init_kernel<<<512, 256>>>();
    proj_kernel<<<592, 256, shmem>>>(x, w_proj, rs, ts);
    edge_pass1<<<(EE + 255) / 256, 256>>>(ei, elen, rds);
    // 8 lanes per edge: 4 edges per warp -> EE/4 warps
    edge_pass2<<<((EE / 4) * 32 + 255) / 256, 256>>>(ei);
    epilogue_kernel<<<(NN + 31) / 32, 256>>>(x, w_out, out);
}

// round 11
// speedup vs baseline: 1.3339x; 1.1897x over previous
#include <cuda_runtime.h>
#include <cuda_fp16.h>

#define NN 50000
#define EE 500000
#define FF 64
#define HH 4

// ---------------- scratch (device globals; no allocation allowed) ----------------
__device__ __align__(16) __half2 g_projh[(size_t)NN * 128]; // [n][h][f] fp16, 25.6 MB
__device__ __align__(16) float2  g_psum2[(size_t)NN * 32];  // [n][f] fp32 sum over heads, 12.8 MB
__device__ __align__(16) float g_sc[NN * 8];                // node scores [rad h0..3, tan h0..3]
__device__ __align__(16) float g_ssum[NN * 8];              // softmax denominators
__device__ __align__(16) float g_ex[(size_t)EE * 8];        // per-edge exp(logit)
__device__ __align__(16) float g_acc[NN * FF];              // scattered messages (head-mean folded)
__device__ __align__(16) float g_wrt[8 * 64];               // wrt[i][f] = sum_g w[h,f,g]*score[h,g]

__device__ __forceinline__ void red_add_v4(float* p, float4 v) {
    asm volatile("red.global.add.v4.f32 [%0], {%1,%2,%3,%4};"
                 :: "l"(p), "f"(v.x), "f"(v.y), "f"(v.z), "f"(v.w) : "memory");
}

// packed fp32 FMA: d = a*b + c  (2 lanes per instruction, FFMA2)
__device__ __forceinline__ float2 fma2(float2 a, float2 b, float2 c) {
    float2 d;
    asm("fma.rn.f32x2 %0, %1, %2, %3;"
        : "=l"(reinterpret_cast<unsigned long long&>(d))
        : "l"(reinterpret_cast<unsigned long long&>(a)),
          "l"(reinterpret_cast<unsigned long long&>(b)),
          "l"(reinterpret_cast<unsigned long long&>(c)));
    return d;
}

// ---------------- init: zero accumulators ----------------
__global__ void init_kernel() {
    int i = blockIdx.x * blockDim.x + threadIdx.x;
    int stride = gridDim.x * blockDim.x;
    for (int j = i; j < NN * FF; j += stride) g_acc[j] = 0.f;
    for (int j = i; j < NN * 8; j += stride) g_ssum[j] = 0.f;
}

// ---------------- wrt[i][f] (fp32, tiny) ----------------
__global__ void wrt_kernel(const float* __restrict__ w_proj,
                           const float* __restrict__ rs,
                           const float* __restrict__ ts) {
    int e = threadIdx.x;            // 512 threads, one per (i,f)
    int i = e >> 6, f = e & 63;
    int h = i & 3;
    const float* sc = (i < 4) ? rs : ts;
    const float* wrow = w_proj + h * 4096 + f * 64;
    float s = 0.f;
    #pragma unroll 8
    for (int g = 0; g < 64; g++) s += wrow[g] * sc[h * 64 + g];
    g_wrt[i * 64 + f] = s;
}

// ---------------- node scores: sc[n,i] = x[n,:] . wrt[i,:]  (fp32) ----------------
__global__ void sc_kernel(const float* __restrict__ x) {
    int t = blockIdx.x * blockDim.x + threadIdx.x;
    int n = t >> 3, i = t & 7;
    if (n >= NN) return;
    const float4* xr = (const float4*)(x + (size_t)n * 64);
    const float4* wr = (const float4*)(g_wrt + i * 64);
    float s = 0.f;
    #pragma unroll
    for (int k = 0; k < 16; k++) {
        float4 a = xr[k], b = wr[k];
        s += a.x * b.x + a.y * b.y + a.z * b.z + a.w * b.w;
    }
    g_sc[n * 8 + i] = s;
}

// ---------------- per-node projection GEMM only (fp32 weights, 72KB smem) ----------
// proj[n,h,g] = sum_f x[n,f] * w_proj[h,f,g]  -> g_projh (fp16), g_psum2 (fp32 sum_h)
// smem: wsh2 64KB (16384 floats) + xs 8KB (2048 floats) = 73728 B = 72KB -> 3 blocks/SM
#define PT 32  // nodes per tile
__global__ void __launch_bounds__(256, 3)
proj_kernel(const float* __restrict__ x,
            const float* __restrict__ w_proj) {
    extern __shared__ float sh[];
    float2* wsh2 = (float2*)sh;          // [64][128]: wsh2[f*128 + h*32 + gp] = w[h,f,2gp..2gp+1]
    float*  xs   = sh + 16384;           // [PT][64], NO padding (reads are warp-broadcast)

    int tid = threadIdx.x;

    // load weights, transposed to [f][h*32+gp]
    for (int idx = tid; idx < 64 * 128; idx += 256) {
        int f = idx >> 7, p = idx & 127;
        int h = p >> 5, gp = p & 31;
        wsh2[idx] = ((const float2*)w_proj)[h * 2048 + f * 32 + gp];
    }

    int pg = tid & 31;       // g-pair column (covers g = 2pg, 2pg+1 of every head)
    int ng = tid >> 5;       // node group (4 nodes each)
    int ntiles = (NN + PT - 1) / PT;

    for (int tile = blockIdx.x; tile < ntiles; tile += gridDim.x) {
        int n0 = tile * PT;
        __syncthreads();  // orders weight load (first iter) and xs across tiles
        for (int idx = tid; idx < PT * 64; idx += 256) {
            int nd = idx >> 6, f = idx & 63;
            int n = n0 + nd;
            xs[nd * 64 + f] = (n < NN) ? x[n * 64 + f] : 0.f;
        }
        __syncthreads();

        float2 acc[4][4];  // [node j][head h] — pair (2pg,2pg+1)
        #pragma unroll
        for (int j = 0; j < 4; j++)
            #pragma unroll
            for (int h = 0; h < 4; h++) acc[j][h] = make_float2(0.f, 0.f);

        #pragma unroll 4
        for (int f = 0; f < 64; f++) {
            float2 w0 = wsh2[f * 128 + pg];
            float2 w1 = wsh2[f * 128 + 32 + pg];
            float2 w2 = wsh2[f * 128 + 64 + pg];
            float2 w3 = wsh2[f * 128 + 96 + pg];
            #pragma unroll
            for (int j = 0; j < 4; j++) {
                float xv = xs[(ng * 4 + j) * 64 + f];  // warp-broadcast read
                float2 xx = make_float2(xv, xv);
                acc[j][0] = fma2(w0, xx, acc[j][0]);
                acc[j][1] = fma2(w1, xx, acc[j][1]);
                acc[j][2] = fma2(w2, xx, acc[j][2]);
                acc[j][3] = fma2(w3, xx, acc[j][3]);
            }
        }

        #pragma unroll
        for (int j = 0; j < 4; j++) {
            int n = n0 + ng * 4 + j;
            if (n < NN) {
                __half2* op = g_projh + (size_t)n * 128;   // [h*32 + pg]
                op[pg]      = __float22half2_rn(acc[j][0]);
                op[32 + pg] = __float22half2_rn(acc[j][1]);
                op[64 + pg] = __float22half2_rn(acc[j][2]);
                op[96 + pg] = __float22half2_rn(acc[j][3]);
                float2 ps;
                ps.x = acc[j][0].x + acc[j][1].x + acc[j][2].x + acc[j][3].x;
                ps.y = acc[j][0].y + acc[j][1].y + acc[j][2].y + acc[j][3].y;
                g_psum2[(size_t)n * 32 + pg] = ps;
            }
        }
    }
}

// ---------------- edge pass 1: exp(logits), accumulate softmax sums ----------------
__global__ void edge_pass1(const int* __restrict__ ei,
                           const float* __restrict__ elen,
                           const float* __restrict__ rds) {
    int i = blockIdx.x * blockDim.x + threadIdx.x;
    if (i >= EE) return;
    float scale = rds[0];
    int s = ei[i], r = ei[EE + i];
    const float4* scp = (const float4*)g_sc;
    float4 a0 = scp[s * 2], a1 = scp[s * 2 + 1];
    float4 b0 = scp[r * 2], b1 = scp[r * 2 + 1];
    float d = scale * elen[i];
    float4 er, et;
    er.x = __expf(a0.x - b0.x - d); er.y = __expf(a0.y - b0.y - d);
    er.z = __expf(a0.z - b0.z - d); er.w = __expf(a0.w - b0.w - d);
    et.x = __expf(a1.x - b1.x);     et.y = __expf(a1.y - b1.y);
    et.z = __expf(a1.z - b1.z);     et.w = __expf(a1.w - b1.w);
    float4* exp_ptr = (float4*)(g_ex + (size_t)i * 8);
    exp_ptr[0] = er;
    exp_ptr[1] = et;
    red_add_v4(g_ssum + r * 8, er);
    red_add_v4(g_ssum + r * 8 + 4, et);
}

// ---------------- edge pass 2: alpha-weighted scatter of fp16 sender proj ------------
// 8 lanes per edge (4 edges per warp); lane sub handles f-chunk [8sub, 8sub+7] of
// every head via one LDG.128 per head (R6 version — measured best)
__global__ void edge_pass2(const int* __restrict__ ei) {
    int lane = threadIdx.x & 31;
    int warp = (blockIdx.x * blockDim.x + threadIdx.x) >> 5;
    int grp = lane >> 3, sub = lane & 7;
    int e = warp * 4 + grp;
    if (e >= EE) return;
    int s = ei[e], r = ei[EE + e];

    // every lane computes one of the 8 alphas
    float a = __fdividef(g_ex[(size_t)e * 8 + sub], g_ssum[r * 8 + sub]);
    // combined per-head weight = alpha_rad[h] + alpha_tan[h]  (shuffle within 8-lane group)
    const unsigned m = 0xffffffffu;
    float w0 = __shfl_sync(m, a, 0, 8) + __shfl_sync(m, a, 4, 8);
    float w1 = __shfl_sync(m, a, 1, 8) + __shfl_sync(m, a, 5, 8);
    float w2 = __shfl_sync(m, a, 2, 8) + __shfl_sync(m, a, 6, 8);
    float w3 = __shfl_sync(m, a, 3, 8) + __shfl_sync(m, a, 7, 8);

    // fp16 row: 256 halves = 32 uint4; head h occupies uint4 [h*8, h*8+7]
    const uint4* ph = (const uint4*)g_projh + (size_t)s * 32;
    uint4 q0 = ph[sub], q1 = ph[8 + sub], q2 = ph[16 + sub], q3 = ph[24 + sub];

    float v[8];
    #pragma unroll
    for (int k = 0; k < 8; k++) v[k] = 0.f;

    #pragma unroll
    for (int h = 0; h < 4; h++) {
        uint4 q = (h == 0) ? q0 : (h == 1) ? q1 : (h == 2) ? q2 : q3;
        float w = (h == 0) ? w0 : (h == 1) ? w1 : (h == 2) ? w2 : w3;
        float2 c0 = __half22float2(*(const __half2*)&q.x);
        float2 c1 = __half22float2(*(const __half2*)&q.y);
        float2 c2 = __half22float2(*(const __half2*)&q.z);
        float2 c3 = __half22float2(*(const __half2*)&q.w);
        v[0] += w * c0.x; v[1] += w * c0.y;
        v[2] += w * c1.x; v[3] += w * c1.y;
        v[4] += w * c2.x; v[5] += w * c2.y;
        v[6] += w * c3.x; v[7] += w * c3.y;
    }
    // 0.25 = head mean, applied once here
    float4 vA = make_float4(0.25f * v[0], 0.25f * v[1], 0.25f * v[2], 0.25f * v[3]);
    float4 vB = make_float4(0.25f * v[4], 0.25f * v[5], 0.25f * v[6], 0.25f * v[7]);
    float* dst = g_acc + r * 64 + sub * 8;
    red_add_v4(dst, vA);
    red_add_v4(dst + 4, vB);
}

// ---------------- epilogue: msg, residual + out-GEMM (packed f32x2) ----------------
// warp handles 4 nodes; lane handles output-column pair (2lane, 2lane+1)
// msg[n,f] = g_acc[n,f] - 0.5*flag*psum[n,f]
__global__ void epilogue_kernel(const float* __restrict__ x,
                                const float* __restrict__ w_out,
                                float* __restrict__ out) {
    __shared__ float2 wsh2[64 * 32];     // [f][gp]
    __shared__ float msh[8][4][64];
    int tid = threadIdx.x, lane = tid & 31, wid = tid >> 5;
    for (int idx = tid; idx < 2048; idx += 256) wsh2[idx] = ((const float2*)w_out)[idx];
    __syncthreads();

    int base = (blockIdx.x * 8 + wid) * 4;
    if (base >= NN) return;

    const float* psum = (const float*)g_psum2;
    #pragma unroll
    for (int j = 0; j < 4; j++) {
        int n = base + j;
        if (n >= NN) { msh[wid][j][lane] = 0.f; msh[wid][j][lane + 32] = 0.f; continue; }
        float ne = (g_ssum[n * 8] > 0.f) ? 0.5f : 0.f;
        #pragma unroll
        for (int k = 0; k < 2; k++) {
            int f = lane + k * 32;
            msh[wid][j][f] = g_acc[n * 64 + f] - ne * psum[(size_t)n * 64 + f];
        }
    }
    __syncwarp();

    float2 a2[4];
    #pragma unroll
    for (int j = 0; j < 4; j++) {
        int n = base + j;
        a2[j] = (n < NN) ? ((const float2*)x)[n * 32 + lane] : make_float2(0.f, 0.f);
    }
    #pragma unroll 4
    for (int f = 0; f < 64; f++) {
        float2 w = wsh2[f * 32 + lane];
        #pragma unroll
        for (int j = 0; j < 4; j++) {
            float m = msh[wid][j][f];
            a2[j] = fma2(w, make_float2(m, m), a2[j]);
        }
    }
    #pragma unroll
    for (int j = 0; j < 4; j++) {
        int n = base + j;
        if (n < NN) ((float2*)out)[n * 32 + lane] = a2[j];
    }
}

// ---------------- launch ----------------
extern "C" void kernel_launch(void* const* d_in, const int* in_sizes, int n_in,
                              void* d_out, int out_size) {
    const float* x      = (const float*)d_in[0];
    const int*   ei     = (const int*)d_in[1];
    // d_in[2] = edge_vec (unused by reference)
    const float* elen   = (const float*)d_in[3];
    const float* w_proj = (const float*)d_in[4];
    const float* rs     = (const float*)d_in[5];
    const float* ts     = (const float*)d_in[6];
    const float* rds    = (const float*)d_in[7];
    const float* w_out  = (const float*)d_in[8];
    float* out = (float*)d_out;

    // proj smem: 16384 (fp32 weights, 64KB) + 2048 (xs, 8KB) = 73728 B = 72KB
    const int shmem = (16384 + PT * 64) * (int)sizeof(float);
    cudaFuncSetAttribute(proj_kernel, cudaFuncAttributeMaxDynamicSharedMemorySize, shmem);

    init_kernel<<<512, 256>>>();
    wrt_kernel<<<1, 512>>>(w_proj, rs, ts);
    sc_kernel<<<(NN * 8 + 255) / 256, 256>>>(x);
    proj_kernel<<<444, 256, shmem>>>(x, w_proj);
    edge_pass1<<<(EE + 255) / 256, 256>>>(ei, elen, rds);
    // 8 lanes per edge: 4 edges per warp -> EE/4 warps
    edge_pass2<<<((EE / 4) * 32 + 255) / 256, 256>>>(ei);
    epilogue_kernel<<<(NN + 31) / 32, 256>>>(x, w_out, out);
}

// round 12
// speedup vs baseline: 1.4400x; 1.0795x over previous
#include <cuda_runtime.h>
#include <cuda_fp16.h>

#define NN 50000
#define EE 500000
#define FF 64
#define HH 4

// ---------------- scratch (device globals; no allocation allowed) ----------------
__device__ __align__(16) __half2 g_projh[(size_t)NN * 128]; // [n][h][f] fp16, 25.6 MB
__device__ __align__(16) float2  g_psum2[(size_t)NN * 32];  // [n][f] fp32 sum over heads, 12.8 MB
__device__ __align__(16) float g_sc[NN * 8];                // node scores [rad h0..3, tan h0..3]
__device__ __align__(16) float g_ssum[NN * 8];              // softmax denominators
__device__ __align__(16) float g_ex[(size_t)EE * 8];        // per-edge exp(logit)
__device__ __align__(16) float g_acc[NN * FF];              // scattered messages (head-mean folded)
__device__ __align__(16) float g_wrt[8 * 64];               // wrt[i][f] = sum_g w[h,f,g]*score[h,g]

__device__ __forceinline__ void red_add_v4(float* p, float4 v) {
    asm volatile("red.global.add.v4.f32 [%0], {%1,%2,%3,%4};"
                 :: "l"(p), "f"(v.x), "f"(v.y), "f"(v.z), "f"(v.w) : "memory");
}

// packed fp32 FMA: d = a*b + c  (2 lanes per instruction, FFMA2)
__device__ __forceinline__ float2 fma2(float2 a, float2 b, float2 c) {
    float2 d;
    asm("fma.rn.f32x2 %0, %1, %2, %3;"
        : "=l"(reinterpret_cast<unsigned long long&>(d))
        : "l"(reinterpret_cast<unsigned long long&>(a)),
          "l"(reinterpret_cast<unsigned long long&>(b)),
          "l"(reinterpret_cast<unsigned long long&>(c)));
    return d;
}

// ---------------- init: zero accumulators; blocks 0-1 also compute wrt ----------------
__global__ void init_kernel(const float* __restrict__ w_proj,
                            const float* __restrict__ rs,
                            const float* __restrict__ ts) {
    int i = blockIdx.x * blockDim.x + threadIdx.x;
    // blocks 0,1: 512 threads compute wrt[i][f] in fp32
    if (blockIdx.x < 2) {
        int e = i;                        // 0..511
        int ii = e >> 6, f = e & 63;
        int h = ii & 3;
        const float* sc = (ii < 4) ? rs : ts;
        const float* wrow = w_proj + h * 4096 + f * 64;
        float s = 0.f;
        #pragma unroll 8
        for (int g = 0; g < 64; g++) s += wrow[g] * sc[h * 64 + g];
        g_wrt[ii * 64 + f] = s;
    }
    int stride = gridDim.x * blockDim.x;
    for (int j = i; j < NN * FF; j += stride) g_acc[j] = 0.f;
    for (int j = i; j < NN * 8; j += stride) g_ssum[j] = 0.f;
}

// ---------------- per-node projection GEMM + node scores ----------
// proj[n,h,g] = sum_f x[n,f] * w_proj[h,f,g]  -> g_projh (fp16), g_psum2 (fp32 sum_h)
// sc[n,i] = sum_f x[n,f]*wrt[i,f]  (wrt read from global, L1-resident 2KB)
// smem: wsh2 64KB (16384 floats) + xs 8KB (2048 floats) = 73728 B = 72KB -> 3 blocks/SM
#define PT 32  // nodes per tile
__global__ void __launch_bounds__(256, 3)
proj_kernel(const float* __restrict__ x,
            const float* __restrict__ w_proj) {
    extern __shared__ float sh[];
    float2* wsh2 = (float2*)sh;          // [64][128]: wsh2[f*128 + h*32 + gp] = w[h,f,2gp..2gp+1]
    float*  xs   = sh + 16384;           // [PT][64], NO padding (reads are warp-broadcast)

    int tid = threadIdx.x;

    // load weights, transposed to [f][h*32+gp]
    for (int idx = tid; idx < 64 * 128; idx += 256) {
        int f = idx >> 7, p = idx & 127;
        int h = p >> 5, gp = p & 31;
        wsh2[idx] = ((const float2*)w_proj)[h * 2048 + f * 32 + gp];
    }

    int pg = tid & 31;       // g-pair column (covers g = 2pg, 2pg+1 of every head)
    int ng = tid >> 5;       // node group (4 nodes each)
    int nd2 = tid >> 3, i2 = tid & 7;   // for sc: node tid/8, score-index tid%8
    int ntiles = (NN + PT - 1) / PT;

    for (int tile = blockIdx.x; tile < ntiles; tile += gridDim.x) {
        int n0 = tile * PT;
        __syncthreads();  // orders weight load (first iter) and xs across tiles
        for (int idx = tid; idx < PT * 64; idx += 256) {
            int nd = idx >> 6, f = idx & 63;
            int n = n0 + nd;
            xs[nd * 64 + f] = (n < NN) ? x[n * 64 + f] : 0.f;
        }
        __syncthreads();

        float2 acc[4][4];  // [node j][head h] — pair (2pg,2pg+1)
        #pragma unroll
        for (int j = 0; j < 4; j++)
            #pragma unroll
            for (int h = 0; h < 4; h++) acc[j][h] = make_float2(0.f, 0.f);

        #pragma unroll 4
        for (int f = 0; f < 64; f++) {
            float2 w0 = wsh2[f * 128 + pg];
            float2 w1 = wsh2[f * 128 + 32 + pg];
            float2 w2 = wsh2[f * 128 + 64 + pg];
            float2 w3 = wsh2[f * 128 + 96 + pg];
            #pragma unroll
            for (int j = 0; j < 4; j++) {
                float xv = xs[(ng * 4 + j) * 64 + f];  // warp-broadcast read
                float2 xx = make_float2(xv, xv);
                acc[j][0] = fma2(w0, xx, acc[j][0]);
                acc[j][1] = fma2(w1, xx, acc[j][1]);
                acc[j][2] = fma2(w2, xx, acc[j][2]);
                acc[j][3] = fma2(w3, xx, acc[j][3]);
            }
        }

        #pragma unroll
        for (int j = 0; j < 4; j++) {
            int n = n0 + ng * 4 + j;
            if (n < NN) {
                __half2* op = g_projh + (size_t)n * 128;   // [h*32 + pg]
                op[pg]      = __float22half2_rn(acc[j][0]);
                op[32 + pg] = __float22half2_rn(acc[j][1]);
                op[64 + pg] = __float22half2_rn(acc[j][2]);
                op[96 + pg] = __float22half2_rn(acc[j][3]);
                float2 ps;
                ps.x = acc[j][0].x + acc[j][1].x + acc[j][2].x + acc[j][3].x;
                ps.y = acc[j][0].y + acc[j][1].y + acc[j][2].y + acc[j][3].y;
                g_psum2[(size_t)n * 32 + pg] = ps;
            }
        }

        // node scores (fp32): xs resident in smem, wrt hot in L1 (2KB)
        int n2 = n0 + nd2;
        if (n2 < NN) {
            const float* wr = g_wrt + i2 * 64;
            float s = 0.f;
            #pragma unroll 8
            for (int f = 0; f < 64; f++) s += xs[nd2 * 64 + f] * __ldg(wr + f);
            g_sc[n2 * 8 + i2] = s;
        }
    }
}

// ---------------- edge pass 1: exp(logits), accumulate softmax sums ----------------
__global__ void edge_pass1(const int* __restrict__ ei,
                           const float* __restrict__ elen,
                           const float* __restrict__ rds) {
    int i = blockIdx.x * blockDim.x + threadIdx.x;
    if (i >= EE) return;
    float scale = rds[0];
    int s = ei[i], r = ei[EE + i];
    const float4* scp = (const float4*)g_sc;
    float4 a0 = scp[s * 2], a1 = scp[s * 2 + 1];
    float4 b0 = scp[r * 2], b1 = scp[r * 2 + 1];
    float d = scale * elen[i];
    float4 er, et;
    er.x = __expf(a0.x - b0.x - d); er.y = __expf(a0.y - b0.y - d);
    er.z = __expf(a0.z - b0.z - d); er.w = __expf(a0.w - b0.w - d);
    et.x = __expf(a1.x - b1.x);     et.y = __expf(a1.y - b1.y);
    et.z = __expf(a1.z - b1.z);     et.w = __expf(a1.w - b1.w);
    float4* exp_ptr = (float4*)(g_ex + (size_t)i * 8);
    exp_ptr[0] = er;
    exp_ptr[1] = et;
    red_add_v4(g_ssum + r * 8, er);
    red_add_v4(g_ssum + r * 8 + 4, et);
}

// ---------------- edge pass 2: alpha-weighted scatter of fp16 sender proj ------------
// 8 lanes per edge (4 edges per warp); lane sub handles f-chunk [8sub, 8sub+7] of
// every head via one LDG.128 per head (R6 version — measured best)
__global__ void edge_pass2(const int* __restrict__ ei) {
    int lane = threadIdx.x & 31;
    int warp = (blockIdx.x * blockDim.x + threadIdx.x) >> 5;
    int grp = lane >> 3, sub = lane & 7;
    int e = warp * 4 + grp;
    if (e >= EE) return;
    int s = ei[e], r = ei[EE + e];

    // every lane computes one of the 8 alphas
    float a = __fdividef(g_ex[(size_t)e * 8 + sub], g_ssum[r * 8 + sub]);
    // combined per-head weight = alpha_rad[h] + alpha_tan[h]  (shuffle within 8-lane group)
    const unsigned m = 0xffffffffu;
    float w0 = __shfl_sync(m, a, 0, 8) + __shfl_sync(m, a, 4, 8);
    float w1 = __shfl_sync(m, a, 1, 8) + __shfl_sync(m, a, 5, 8);
    float w2 = __shfl_sync(m, a, 2, 8) + __shfl_sync(m, a, 6, 8);
    float w3 = __shfl_sync(m, a, 3, 8) + __shfl_sync(m, a, 7, 8);

    // fp16 row: 256 halves = 32 uint4; head h occupies uint4 [h*8, h*8+7]
    const uint4* ph = (const uint4*)g_projh + (size_t)s * 32;
    uint4 q0 = ph[sub], q1 = ph[8 + sub], q2 = ph[16 + sub], q3 = ph[24 + sub];

    float v[8];
    #pragma unroll
    for (int k = 0; k < 8; k++) v[k] = 0.f;

    #pragma unroll
    for (int h = 0; h < 4; h++) {
        uint4 q = (h == 0) ? q0 : (h == 1) ? q1 : (h == 2) ? q2 : q3;
        float w = (h == 0) ? w0 : (h == 1) ? w1 : (h == 2) ? w2 : w3;
        float2 c0 = __half22float2(*(const __half2*)&q.x);
        float2 c1 = __half22float2(*(const __half2*)&q.y);
        float2 c2 = __half22float2(*(const __half2*)&q.z);
        float2 c3 = __half22float2(*(const __half2*)&q.w);
        v[0] += w * c0.x; v[1] += w * c0.y;
        v[2] += w * c1.x; v[3] += w * c1.y;
        v[4] += w * c2.x; v[5] += w * c2.y;
        v[6] += w * c3.x; v[7] += w * c3.y;
    }
    // 0.25 = head mean, applied once here
    float4 vA = make_float4(0.25f * v[0], 0.25f * v[1], 0.25f * v[2], 0.25f * v[3]);
    float4 vB = make_float4(0.25f * v[4], 0.25f * v[5], 0.25f * v[6], 0.25f * v[7]);
    float* dst = g_acc + r * 64 + sub * 8;
    red_add_v4(dst, vA);
    red_add_v4(dst + 4, vB);
}

// ---------------- epilogue: msg, residual + out-GEMM (packed f32x2) ----------------
// warp handles 4 nodes; lane handles output-column pair (2lane, 2lane+1)
// msg[n,f] = g_acc[n,f] - 0.5*flag*psum[n,f]
__global__ void epilogue_kernel(const float* __restrict__ x,
                                const float* __restrict__ w_out,
                                float* __restrict__ out) {
    __shared__ float2 wsh2[64 * 32];     // [f][gp]
    __shared__ float msh[8][4][64];
    int tid = threadIdx.x, lane = tid & 31, wid = tid >> 5;
    for (int idx = tid; idx < 2048; idx += 256) wsh2[idx] = ((const float2*)w_out)[idx];
    __syncthreads();

    int base = (blockIdx.x * 8 + wid) * 4;
    if (base >= NN) return;

    const float* psum = (const float*)g_psum2;
    #pragma unroll
    for (int j = 0; j < 4; j++) {
        int n = base + j;
        if (n >= NN) { msh[wid][j][lane] = 0.f; msh[wid][j][lane + 32] = 0.f; continue; }
        float ne = (g_ssum[n * 8] > 0.f) ? 0.5f : 0.f;
        #pragma unroll
        for (int k = 0; k < 2; k++) {
            int f = lane + k * 32;
            msh[wid][j][f] = g_acc[n * 64 + f] - ne * psum[(size_t)n * 64 + f];
        }
    }
    __syncwarp();

    float2 a2[4];
    #pragma unroll
    for (int j = 0; j < 4; j++) {
        int n = base + j;
        a2[j] = (n < NN) ? ((const float2*)x)[n * 32 + lane] : make_float2(0.f, 0.f);
    }
    #pragma unroll 4
    for (int f = 0; f < 64; f++) {
        float2 w = wsh2[f * 32 + lane];
        #pragma unroll
        for (int j = 0; j < 4; j++) {
            float m = msh[wid][j][f];
            a2[j] = fma2(w, make_float2(m, m), a2[j]);
        }
    }
    #pragma unroll
    for (int j = 0; j < 4; j++) {
        int n = base + j;
        if (n < NN) ((float2*)out)[n * 32 + lane] = a2[j];
    }
}

// ---------------- launch ----------------
extern "C" void kernel_launch(void* const* d_in, const int* in_sizes, int n_in,
                              void* d_out, int out_size) {
    const float* x      = (const float*)d_in[0];
    const int*   ei     = (const int*)d_in[1];
    // d_in[2] = edge_vec (unused by reference)
    const float* elen   = (const float*)d_in[3];
    const float* w_proj = (const float*)d_in[4];
    const float* rs     = (const float*)d_in[5];
    const float* ts     = (const float*)d_in[6];
    const float* rds    = (const float*)d_in[7];
    const float* w_out  = (const float*)d_in[8];
    float* out = (float*)d_out;

    // proj smem: 16384 (fp32 weights, 64KB) + 2048 (xs, 8KB) = 73728 B = 72KB
    const int shmem = (16384 + PT * 64) * (int)sizeof(float);
    cudaFuncSetAttribute(proj_kernel, cudaFuncAttributeMaxDynamicSharedMemorySize, shmem);

    init_kernel<<<512, 256>>>(w_proj, rs, ts);
    proj_kernel<<<444, 256, shmem>>>(x, w_proj);
    edge_pass1<<<(EE + 255) / 256, 256>>>(ei, elen, rds);
    // 8 lanes per edge: 4 edges per warp -> EE/4 warps
    edge_pass2<<<((EE / 4) * 32 + 255) / 256, 256>>>(ei);
    epilogue_kernel<<<(NN + 31) / 32, 256>>>(x, w_out, out);
}